// round 1
// baseline (speedup 1.0000x reference)
#include <cuda_runtime.h>
#include <math.h>

// Problem constants
#define Mm 4
#define Pp 4
#define Ll 2
#define Ss 256
#define Bb 32
#define Ii 256
#define Hh 512
#define Oo 256
#define Gg (3*Hh)     // 1536
#define Rr (Pp*Bb)    // 128 rows per model in the recurrence

// ---------------- scratch (device globals; no allocation) ----------------
__device__ float g_gi0[(size_t)Mm*Ss*Bb*Gg];        // 50,331,648  (201 MB)
__device__ float g_y0m[(size_t)Mm*Pp*Ss*Bb*Hh];     // 67,108,864  (268 MB) masked layer-0 output
__device__ float g_gi1[(size_t)Mm*Pp*Ss*Bb*Gg];     // 201,326,592 (805 MB)
__device__ float g_a1 [(size_t)Mm*Pp*Ss*Bb*Hh];     // 67,108,864  (268 MB) leakyrelu(layer-1 output)
__device__ float g_h0a[Mm*Rr*Hh];
__device__ float g_h0b[Mm*Rr*Hh];
__device__ float g_h1a[Mm*Rr*Hh];
__device__ float g_h1b[Mm*Rr*Hh];

// ---------------- init hidden: [M,P,L,B,H] -> per-layer [M][R][H] ----------------
__global__ void init_hidden_kernel(const float* __restrict__ hidden,
                                   float* __restrict__ h0, float* __restrict__ h1)
{
    int idx = blockIdx.x * blockDim.x + threadIdx.x;
    const int n = Mm*Pp*Bb*Hh;
    if (idx >= n) return;
    int mp  = idx / (Bb*Hh);
    int rem = idx % (Bb*Hh);
    h0[idx] = hidden[((size_t)mp*Ll + 0)*Bb*Hh + rem];
    h1[idx] = hidden[((size_t)mp*Ll + 1)*Bb*Hh + rem];
}

// ---------------- hidden out: per-layer [M][R][H] -> [M,P,L,B,H] ----------------
__global__ void hidden_out_kernel(const float* __restrict__ h0, const float* __restrict__ h1,
                                  float* __restrict__ out)
{
    int idx = blockIdx.x * blockDim.x + threadIdx.x;
    const int n = Mm*Pp*Bb*Hh;
    if (idx >= n) return;
    int mp  = idx / (Bb*Hh);
    int rem = idx % (Bb*Hh);
    out[((size_t)mp*Ll + 0)*Bb*Hh + rem] = h0[idx];
    out[((size_t)mp*Ll + 1)*Bb*Hh + rem] = h1[idx];
}

// ---------------- generic batched SGEMM with bias: C = A @ W^T + bias ----------------
// A: [rows, K] (per-batch stride aStride; 0 => shared)
// W: [N, K]    (per-batch stride wStride)
// C: [rows, N] (per-batch stride cStride)
// BM=128, BN=64, BK=16, 256 threads, 8x4 micro-tile.
__global__ void gemm_bias_kernel(const float* __restrict__ A, long aStride,
                                 const float* __restrict__ W, long wStride,
                                 const float* __restrict__ bias, int bStride,
                                 float* __restrict__ C, long cStride,
                                 int rows, int N, int K)
{
    const int BM = 128, BN = 64, BK = 16;
    const int batch = blockIdx.z;
    A    += (long)batch * aStride;
    W    += (long)batch * wStride;
    bias += (long)batch * bStride;
    C    += (long)batch * cStride;

    const int row0 = blockIdx.y * BM;
    const int col0 = blockIdx.x * BN;

    __shared__ float As[BK][BM];
    __shared__ float Bs[BK][BN];

    const int tid = threadIdx.x;
    const int tx = tid & 15, ty = tid >> 4;
    const int TM = 8, TN = 4;

    float acc[TM][TN];
#pragma unroll
    for (int i = 0; i < TM; i++)
#pragma unroll
        for (int j = 0; j < TN; j++) acc[i][j] = 0.f;

    for (int k0 = 0; k0 < K; k0 += BK) {
        // A tile: 128x16 -> 512 float4, 2 per thread, transposed into As[k][m]
#pragma unroll
        for (int l = 0; l < 2; l++) {
            int f = tid + l * 256;
            int m = f >> 2;
            int kg = f & 3;
            float4 v = *reinterpret_cast<const float4*>(&A[(long)(row0 + m) * K + k0 + kg * 4]);
            As[kg*4+0][m] = v.x; As[kg*4+1][m] = v.y; As[kg*4+2][m] = v.z; As[kg*4+3][m] = v.w;
        }
        // W tile: 64x16 -> 256 float4, 1 per thread
        {
            int f = tid;
            int n = f >> 2;
            int kg = f & 3;
            float4 v = *reinterpret_cast<const float4*>(&W[(long)(col0 + n) * K + k0 + kg * 4]);
            Bs[kg*4+0][n] = v.x; Bs[kg*4+1][n] = v.y; Bs[kg*4+2][n] = v.z; Bs[kg*4+3][n] = v.w;
        }
        __syncthreads();
#pragma unroll
        for (int kk = 0; kk < BK; kk++) {
            float a[TM], b[TN];
#pragma unroll
            for (int i = 0; i < TM; i++) a[i] = As[kk][ty * TM + i];
#pragma unroll
            for (int j = 0; j < TN; j++) b[j] = Bs[kk][tx * TN + j];
#pragma unroll
            for (int i = 0; i < TM; i++)
#pragma unroll
                for (int j = 0; j < TN; j++)
                    acc[i][j] += a[i] * b[j];
        }
        __syncthreads();
    }

#pragma unroll
    for (int i = 0; i < TM; i++) {
        int r = row0 + ty * TM + i;
#pragma unroll
        for (int j = 0; j < TN; j++) {
            int c = col0 + tx * TN + j;
            C[(long)r * N + c] = acc[i][j] + bias[c];
        }
    }
}

// ---------------- fused GRU step: gh GEMM + gates + h update + activation store ----------------
// grid: (Hh/32=16, Rr/64=2, Mm=4), 256 threads.
// Each block: rows [r0,r0+64), h-cols [j0,j0+32), 3 gates fused per (r,j) in registers.
__device__ __forceinline__ float sigmoidf_(float x) { return 1.0f / (1.0f + expf(-x)); }

template<int LAYER>
__global__ void gru_step_kernel(const float* __restrict__ hprev,
                                float* __restrict__ hnext,
                                const float* __restrict__ gi,   // full gi tensor
                                const float* __restrict__ whh,  // [M][3H][H]
                                const float* __restrict__ bhh,  // [M][3H]
                                const float* __restrict__ dm,   // drop mask [M,P,S,B,H] (layer0)
                                float* __restrict__ outact,     // [M,P,S,B,H]
                                int t)
{
    const int BK = 32;
    const int m  = blockIdx.z;
    const int r0 = blockIdx.y * 64;
    const int j0 = blockIdx.x * 32;

    __shared__ float As[BK][64];
    __shared__ float Bs[BK][96];

    const int tid = threadIdx.x;
    const int tx = tid & 15, ty = tid >> 4;

    float acc[4][3][2];   // [row][gate][jj]
#pragma unroll
    for (int i = 0; i < 4; i++)
#pragma unroll
        for (int g = 0; g < 3; g++) { acc[i][g][0] = 0.f; acc[i][g][1] = 0.f; }

    const float* Ab = hprev + (long)m * Rr * Hh;   // [128][512]
    const float* Wb = whh   + (long)m * Gg * Hh;

    for (int k0 = 0; k0 < Hh; k0 += BK) {
        // A tile: 64 rows x 32 k = 512 float4, 2/thread
#pragma unroll
        for (int l = 0; l < 2; l++) {
            int f = tid + l * 256;
            int row = f >> 3;
            int kg  = f & 7;
            float4 v = *reinterpret_cast<const float4*>(&Ab[(long)(r0 + row) * Hh + k0 + kg * 4]);
            As[kg*4+0][row] = v.x; As[kg*4+1][row] = v.y; As[kg*4+2][row] = v.z; As[kg*4+3][row] = v.w;
        }
        // W tile: 96 gate-cols x 32 k = 768 float4, 3/thread
#pragma unroll
        for (int l = 0; l < 3; l++) {
            int f = tid + l * 256;
            int c  = f >> 3;           // 0..95
            int kg = f & 7;
            int gate = c >> 5;
            int j    = j0 + (c & 31);
            float4 v = *reinterpret_cast<const float4*>(&Wb[(long)(gate * Hh + j) * Hh + k0 + kg * 4]);
            Bs[kg*4+0][c] = v.x; Bs[kg*4+1][c] = v.y; Bs[kg*4+2][c] = v.z; Bs[kg*4+3][c] = v.w;
        }
        __syncthreads();
#pragma unroll
        for (int kk = 0; kk < BK; kk++) {
            float a[4];
#pragma unroll
            for (int i = 0; i < 4; i++) a[i] = As[kk][ty * 4 + i];
            float b[3][2];
#pragma unroll
            for (int g = 0; g < 3; g++) {
                b[g][0] = Bs[kk][g * 32 + tx * 2 + 0];
                b[g][1] = Bs[kk][g * 32 + tx * 2 + 1];
            }
#pragma unroll
            for (int i = 0; i < 4; i++)
#pragma unroll
                for (int g = 0; g < 3; g++) {
                    acc[i][g][0] += a[i] * b[g][0];
                    acc[i][g][1] += a[i] * b[g][1];
                }
        }
        __syncthreads();
    }

    // epilogue: gates + h update
#pragma unroll
    for (int i = 0; i < 4; i++) {
        int r = r0 + ty * 4 + i;
        int p = r >> 5;
        int b = r & 31;
#pragma unroll
        for (int jj = 0; jj < 2; jj++) {
            int j = j0 + tx * 2 + jj;
            long girow;
            if (LAYER == 0)
                girow = ((long)(m * Ss + t) * Bb + b) * Gg;
            else
                girow = ((long)((m * Pp + p) * Ss + t) * Bb + b) * Gg;
            float gir = gi[girow + j];
            float giz = gi[girow + Hh + j];
            float gin = gi[girow + 2 * Hh + j];
            float ghr = acc[i][0][jj] + bhh[m * Gg + j];
            float ghz = acc[i][1][jj] + bhh[m * Gg + Hh + j];
            float ghn = acc[i][2][jj] + bhh[m * Gg + 2 * Hh + j];
            float rg = sigmoidf_(gir + ghr);
            float zg = sigmoidf_(giz + ghz);
            float ng = tanhf(gin + rg * ghn);
            float hold = Ab[(long)r * Hh + j];
            float hnew = (1.0f - zg) * ng + zg * hold;
            hnext[(long)m * Rr * Hh + (long)r * Hh + j] = hnew;
            long oidx = (((long)(m * Pp + p) * Ss + t) * Bb + b) * Hh + j;
            if (LAYER == 0)
                outact[oidx] = hnew * dm[oidx];
            else
                outact[oidx] = fmaxf(hnew, 0.f) + 0.01f * fminf(hnew, 0.f);  // LeakyReLU
        }
    }
}

// ---------------- mean / var over the 16 (m,p) samples ----------------
__global__ void meanvar_kernel(const float* __restrict__ preds,
                               float* __restrict__ out_mean, float* __restrict__ out_var)
{
    const int n = Ss * Bb * Oo;
    int idx = blockIdx.x * blockDim.x + threadIdx.x;
    if (idx >= n) return;
    float v[16];
    float s = 0.f;
#pragma unroll
    for (int mp = 0; mp < 16; mp++) {
        v[mp] = preds[(long)mp * n + idx];
        s += v[mp];
    }
    float mu = s * (1.0f / 16.0f);
    float q = 0.f;
#pragma unroll
    for (int mp = 0; mp < 16; mp++) {
        float d = v[mp] - mu;
        q += d * d;
    }
    out_mean[idx] = mu;
    out_var[idx]  = q * (1.0f / 15.0f);   // unbiased (ddof=1)
}

// ---------------- host launch ----------------
extern "C" void kernel_launch(void* const* d_in, const int* in_sizes, int n_in,
                              void* d_out, int out_size)
{
    const float* input  = (const float*)d_in[0];
    const float* hidden = (const float*)d_in[1];
    const float* w_ih0  = (const float*)d_in[2];
    const float* w_hh0  = (const float*)d_in[3];
    const float* b_ih0  = (const float*)d_in[4];
    const float* b_hh0  = (const float*)d_in[5];
    const float* w_ih1  = (const float*)d_in[6];
    const float* w_hh1  = (const float*)d_in[7];
    const float* b_ih1  = (const float*)d_in[8];
    const float* b_hh1  = (const float*)d_in[9];
    const float* lin_w  = (const float*)d_in[10];
    const float* lin_b  = (const float*)d_in[11];
    const float* dm     = (const float*)d_in[12];

    float* out = (float*)d_out;
    float* out_mean   = out;
    float* out_var    = out + (size_t)Ss * Bb * Oo;
    float* preds      = out + 2 * (size_t)Ss * Bb * Oo;
    float* hidden_out = preds + (size_t)Mm * Pp * Ss * Bb * Oo;

    float *gi0, *y0m, *gi1, *a1, *h0a, *h0b, *h1a, *h1b;
    cudaGetSymbolAddress((void**)&gi0, g_gi0);
    cudaGetSymbolAddress((void**)&y0m, g_y0m);
    cudaGetSymbolAddress((void**)&gi1, g_gi1);
    cudaGetSymbolAddress((void**)&a1,  g_a1);
    cudaGetSymbolAddress((void**)&h0a, g_h0a);
    cudaGetSymbolAddress((void**)&h0b, g_h0b);
    cudaGetSymbolAddress((void**)&h1a, g_h1a);
    cudaGetSymbolAddress((void**)&h1b, g_h1b);

    // 1) init hidden
    init_hidden_kernel<<<(Mm*Pp*Bb*Hh + 255) / 256, 256>>>(hidden, h0a, h1a);

    // 2) gi0 = input @ w_ih0^T + b_ih0  (A shared across models)
    {
        dim3 grid(Gg / 64, (Ss * Bb) / 128, Mm);
        gemm_bias_kernel<<<grid, 256>>>(input, 0L,
                                        w_ih0, (long)Gg * Ii,
                                        b_ih0, Gg,
                                        gi0, (long)Ss * Bb * Gg,
                                        Ss * Bb, Gg, Ii);
    }

    // 3) layer-0 recurrence (double buffered)
    {
        dim3 grid(Hh / 32, Rr / 64, Mm);
        float* hp = h0a; float* hn = h0b;
        for (int t = 0; t < Ss; t++) {
            gru_step_kernel<0><<<grid, 256>>>(hp, hn, gi0, w_hh0, b_hh0, dm, y0m, t);
            float* tmp = hp; hp = hn; hn = tmp;
        }
        // final layer-0 hidden now in hp (h0a, since Ss even)
    }

    // 4) gi1 = y0m @ w_ih1^T + b_ih1
    {
        dim3 grid(Gg / 64, (Pp * Ss * Bb) / 128, Mm);
        gemm_bias_kernel<<<grid, 256>>>(y0m, (long)Pp * Ss * Bb * Hh,
                                        w_ih1, (long)Gg * Hh,
                                        b_ih1, Gg,
                                        gi1, (long)Pp * Ss * Bb * Gg,
                                        Pp * Ss * Bb, Gg, Hh);
    }

    // 5) layer-1 recurrence
    {
        dim3 grid(Hh / 32, Rr / 64, Mm);
        float* hp = h1a; float* hn = h1b;
        for (int t = 0; t < Ss; t++) {
            gru_step_kernel<1><<<grid, 256>>>(hp, hn, gi1, w_hh1, b_hh1, nullptr, a1, t);
            float* tmp = hp; hp = hn; hn = tmp;
        }
    }

    // 6) preds = a1 @ lin_w^T + lin_b  (directly into output)
    {
        dim3 grid(Oo / 64, (Pp * Ss * Bb) / 128, Mm);
        gemm_bias_kernel<<<grid, 256>>>(a1, (long)Pp * Ss * Bb * Hh,
                                        lin_w, (long)Oo * Hh,
                                        lin_b, Oo,
                                        preds, (long)Pp * Ss * Bb * Oo,
                                        Pp * Ss * Bb, Oo, Hh);
    }

    // 7) mean / var
    meanvar_kernel<<<(Ss * Bb * Oo + 255) / 256, 256>>>(preds, out_mean, out_var);

    // 8) hidden out (final buffers: even #steps -> back in the 'a' buffers)
    hidden_out_kernel<<<(Mm*Pp*Bb*Hh + 255) / 256, 256>>>(h0a, h1a, hidden_out);
}

// round 2
// speedup vs baseline: 1.3694x; 1.3694x over previous
#include <cuda_runtime.h>
#include <math.h>
#include <stdint.h>

// Problem constants
#define Mm 4
#define Pp 4
#define Ll 2
#define Ss 256
#define Bb 32
#define Ii 256
#define Hh 512
#define Oo 256
#define Gg (3*Hh)     // 1536
#define Rr (Pp*Bb)    // 128 rows per model in the recurrence

// ---------------- scratch (device globals; no allocation) ----------------
__device__ float g_gi0[(size_t)Mm*Ss*Bb*Gg];
__device__ float g_y0m[(size_t)Mm*Pp*Ss*Bb*Hh];
__device__ float g_gi1[(size_t)Mm*Pp*Ss*Bb*Gg];
__device__ float g_a1 [(size_t)Mm*Pp*Ss*Bb*Hh];
__device__ float g_h0a[Mm*Rr*Hh];
__device__ float g_h0b[Mm*Rr*Hh];
__device__ float g_h1a[Mm*Rr*Hh];
__device__ float g_h1b[Mm*Rr*Hh];

// ---------------- init hidden: [M,P,L,B,H] -> per-layer [M][R][H] ----------------
__global__ void init_hidden_kernel(const float* __restrict__ hidden,
                                   float* __restrict__ h0, float* __restrict__ h1)
{
    int idx = blockIdx.x * blockDim.x + threadIdx.x;
    const int n = Mm*Pp*Bb*Hh;
    if (idx >= n) return;
    int mp  = idx / (Bb*Hh);
    int rem = idx % (Bb*Hh);
    h0[idx] = hidden[((size_t)mp*Ll + 0)*Bb*Hh + rem];
    h1[idx] = hidden[((size_t)mp*Ll + 1)*Bb*Hh + rem];
}

__global__ void hidden_out_kernel(const float* __restrict__ h0, const float* __restrict__ h1,
                                  float* __restrict__ out)
{
    int idx = blockIdx.x * blockDim.x + threadIdx.x;
    const int n = Mm*Pp*Bb*Hh;
    if (idx >= n) return;
    int mp  = idx / (Bb*Hh);
    int rem = idx % (Bb*Hh);
    out[((size_t)mp*Ll + 0)*Bb*Hh + rem] = h0[idx];
    out[((size_t)mp*Ll + 1)*Bb*Hh + rem] = h1[idx];
}

// ================= TF32 tensor-core GEMM with bias: C = A @ W^T + bias =================
// A: [rows, K] row-major (per-batch stride aStride; 0 => shared)
// W: [N, K]   row-major (so W^T is col-major k-contiguous -> mma "col" B operand)
// C: [rows, N]
// BM=128, BN=64, BK=32, 256 threads (8 warps in 4x2), warp tile 32x32 via m16n8k8.

__device__ __forceinline__ float tf32r(float x) {
    uint32_t u;
    asm("cvt.rna.tf32.f32 %0, %1;" : "=r"(u) : "f"(x));
    return __uint_as_float(u);
}

__device__ __forceinline__ void mma_tf32(float c[4], const uint32_t a[4], const uint32_t b[2]) {
    asm volatile(
        "mma.sync.aligned.m16n8k8.row.col.f32.tf32.tf32.f32 "
        "{%0,%1,%2,%3},{%4,%5,%6,%7},{%8,%9},{%0,%1,%2,%3};"
        : "+f"(c[0]), "+f"(c[1]), "+f"(c[2]), "+f"(c[3])
        : "r"(a[0]), "r"(a[1]), "r"(a[2]), "r"(a[3]), "r"(b[0]), "r"(b[1]));
}

__global__ __launch_bounds__(256) void gemm_tf32_bias(
    const float* __restrict__ A, long aStride,
    const float* __restrict__ W, long wStride,
    const float* __restrict__ bias, int bStride,
    float* __restrict__ C, long cStride,
    int rows, int N, int K)
{
    const int batch = blockIdx.z;
    A    += (long)batch * aStride;
    W    += (long)batch * wStride;
    bias += (long)batch * bStride;
    C    += (long)batch * cStride;

    const int r0 = blockIdx.y * 128;
    const int n0 = blockIdx.x * 64;

    __shared__ float As[128][36];
    __shared__ float Bs[64][36];

    const int tid  = threadIdx.x;
    const int lane = tid & 31;
    const int w    = tid >> 5;
    const int wr   = w >> 1;   // 0..3
    const int wc   = w & 1;    // 0..1
    const int gID  = lane >> 2;
    const int tig  = lane & 3;

    float c[2][4][4];
#pragma unroll
    for (int mi = 0; mi < 2; mi++)
#pragma unroll
        for (int ni = 0; ni < 4; ni++)
#pragma unroll
            for (int q = 0; q < 4; q++) c[mi][ni][q] = 0.f;

    for (int k0 = 0; k0 < K; k0 += 32) {
        // A tile 128x32 -> 4 float4 per thread
#pragma unroll
        for (int l = 0; l < 4; l++) {
            int f = tid + l * 256;
            int row = f >> 3;
            int kg  = f & 7;
            float4 v = *reinterpret_cast<const float4*>(&A[(long)(r0 + row) * K + k0 + kg * 4]);
            float4 t;
            t.x = tf32r(v.x); t.y = tf32r(v.y); t.z = tf32r(v.z); t.w = tf32r(v.w);
            *reinterpret_cast<float4*>(&As[row][kg * 4]) = t;
        }
        // B tile 64x32 -> 2 float4 per thread
#pragma unroll
        for (int l = 0; l < 2; l++) {
            int f = tid + l * 256;
            int col = f >> 3;
            int kg  = f & 7;
            float4 v = *reinterpret_cast<const float4*>(&W[(long)(n0 + col) * K + k0 + kg * 4]);
            float4 t;
            t.x = tf32r(v.x); t.y = tf32r(v.y); t.z = tf32r(v.z); t.w = tf32r(v.w);
            *reinterpret_cast<float4*>(&Bs[col][kg * 4]) = t;
        }
        __syncthreads();

#pragma unroll
        for (int k8 = 0; k8 < 4; k8++) {
            const int kb = k8 * 8;
            uint32_t af[2][4];
#pragma unroll
            for (int mi = 0; mi < 2; mi++) {
                int rb = wr * 32 + mi * 16 + gID;
                af[mi][0] = __float_as_uint(As[rb    ][kb + tig]);
                af[mi][1] = __float_as_uint(As[rb + 8][kb + tig]);
                af[mi][2] = __float_as_uint(As[rb    ][kb + 4 + tig]);
                af[mi][3] = __float_as_uint(As[rb + 8][kb + 4 + tig]);
            }
            uint32_t bf[4][2];
#pragma unroll
            for (int ni = 0; ni < 4; ni++) {
                int cb = wc * 32 + ni * 8 + gID;
                bf[ni][0] = __float_as_uint(Bs[cb][kb + tig]);
                bf[ni][1] = __float_as_uint(Bs[cb][kb + 4 + tig]);
            }
#pragma unroll
            for (int mi = 0; mi < 2; mi++)
#pragma unroll
                for (int ni = 0; ni < 4; ni++)
                    mma_tf32(c[mi][ni], af[mi], bf[ni]);
        }
        __syncthreads();
    }

    // epilogue: add bias, store fp32
#pragma unroll
    for (int mi = 0; mi < 2; mi++) {
#pragma unroll
        for (int ni = 0; ni < 4; ni++) {
            int row = r0 + wr * 32 + mi * 16 + gID;
            int col = n0 + wc * 32 + ni * 8 + 2 * tig;
            float b0 = bias[col], b1 = bias[col + 1];
            float2 v0 = make_float2(c[mi][ni][0] + b0, c[mi][ni][1] + b1);
            float2 v1 = make_float2(c[mi][ni][2] + b0, c[mi][ni][3] + b1);
            *reinterpret_cast<float2*>(&C[(long)row * N + col]) = v0;
            *reinterpret_cast<float2*>(&C[(long)(row + 8) * N + col]) = v1;
        }
    }
}

// ================= fused GRU step (fp32, double-buffered) =================
// grid: (Hh/32=16, Rr/64=2, Mm=4), 256 threads. BM=64 rows, 32 j-cols x 3 gates.
__device__ __forceinline__ float sigmoidf_(float x) { return 1.0f / (1.0f + expf(-x)); }

template<int LAYER>
__global__ __launch_bounds__(256) void gru_step_kernel(
    const float* __restrict__ hprev,
    float* __restrict__ hnext,
    const float* __restrict__ gi,
    const float* __restrict__ whh,
    const float* __restrict__ bhh,
    const float* __restrict__ dm,
    float* __restrict__ outact,
    int t)
{
    const int m  = blockIdx.z;
    const int r0 = blockIdx.y * 64;
    const int j0 = blockIdx.x * 32;

    __shared__ float As[2][32][64];
    __shared__ float Bs[2][32][96];

    const int tid = threadIdx.x;
    const int tx = tid & 15, ty = tid >> 4;

    float acc[4][3][2];
#pragma unroll
    for (int i = 0; i < 4; i++)
#pragma unroll
        for (int g = 0; g < 3; g++) { acc[i][g][0] = 0.f; acc[i][g][1] = 0.f; }

    const float* Ab = hprev + (long)m * Rr * Hh;
    const float* Wb = whh   + (long)m * Gg * Hh;

    // per-thread global load slots
    int arow[2], akg[2];
    const float* pA[2];
#pragma unroll
    for (int l = 0; l < 2; l++) {
        int f = tid + l * 256;
        arow[l] = f >> 3;
        akg[l]  = f & 7;
        pA[l] = Ab + (long)(r0 + arow[l]) * Hh + akg[l] * 4;
    }
    int bcol[3], bkg[3];
    const float* pB[3];
#pragma unroll
    for (int l = 0; l < 3; l++) {
        int f = tid + l * 256;
        int cc = f >> 3;          // 0..95
        bkg[l] = f & 7;
        bcol[l] = cc;
        int gate = cc >> 5;
        int j = j0 + (cc & 31);
        pB[l] = Wb + (long)(gate * Hh + j) * Hh + bkg[l] * 4;
    }

    float4 av[2], bv[3];
    // prologue: tile 0
#pragma unroll
    for (int l = 0; l < 2; l++) av[l] = *reinterpret_cast<const float4*>(pA[l]);
#pragma unroll
    for (int l = 0; l < 3; l++) bv[l] = *reinterpret_cast<const float4*>(pB[l]);
#pragma unroll
    for (int l = 0; l < 2; l++) {
        As[0][akg[l]*4+0][arow[l]] = av[l].x;
        As[0][akg[l]*4+1][arow[l]] = av[l].y;
        As[0][akg[l]*4+2][arow[l]] = av[l].z;
        As[0][akg[l]*4+3][arow[l]] = av[l].w;
    }
#pragma unroll
    for (int l = 0; l < 3; l++) {
        Bs[0][bkg[l]*4+0][bcol[l]] = bv[l].x;
        Bs[0][bkg[l]*4+1][bcol[l]] = bv[l].y;
        Bs[0][bkg[l]*4+2][bcol[l]] = bv[l].z;
        Bs[0][bkg[l]*4+3][bcol[l]] = bv[l].w;
    }
    __syncthreads();

    for (int kt = 0; kt < 16; kt++) {
        const int p = kt & 1;
        if (kt < 15) {
            const int off = (kt + 1) * 32;
#pragma unroll
            for (int l = 0; l < 2; l++) av[l] = *reinterpret_cast<const float4*>(pA[l] + off);
#pragma unroll
            for (int l = 0; l < 3; l++) bv[l] = *reinterpret_cast<const float4*>(pB[l] + off);
        }

#pragma unroll 8
        for (int kk = 0; kk < 32; kk++) {
            float4 a = *reinterpret_cast<const float4*>(&As[p][kk][ty * 4]);
            float2 b0 = *reinterpret_cast<const float2*>(&Bs[p][kk][ 0 + tx * 2]);
            float2 b1 = *reinterpret_cast<const float2*>(&Bs[p][kk][32 + tx * 2]);
            float2 b2 = *reinterpret_cast<const float2*>(&Bs[p][kk][64 + tx * 2]);
            float ar[4] = {a.x, a.y, a.z, a.w};
#pragma unroll
            for (int i = 0; i < 4; i++) {
                acc[i][0][0] += ar[i] * b0.x;  acc[i][0][1] += ar[i] * b0.y;
                acc[i][1][0] += ar[i] * b1.x;  acc[i][1][1] += ar[i] * b1.y;
                acc[i][2][0] += ar[i] * b2.x;  acc[i][2][1] += ar[i] * b2.y;
            }
        }

        if (kt < 15) {
            const int q = p ^ 1;
#pragma unroll
            for (int l = 0; l < 2; l++) {
                As[q][akg[l]*4+0][arow[l]] = av[l].x;
                As[q][akg[l]*4+1][arow[l]] = av[l].y;
                As[q][akg[l]*4+2][arow[l]] = av[l].z;
                As[q][akg[l]*4+3][arow[l]] = av[l].w;
            }
#pragma unroll
            for (int l = 0; l < 3; l++) {
                Bs[q][bkg[l]*4+0][bcol[l]] = bv[l].x;
                Bs[q][bkg[l]*4+1][bcol[l]] = bv[l].y;
                Bs[q][bkg[l]*4+2][bcol[l]] = bv[l].z;
                Bs[q][bkg[l]*4+3][bcol[l]] = bv[l].w;
            }
            __syncthreads();
        }
    }

    // epilogue: gates + h update
#pragma unroll
    for (int i = 0; i < 4; i++) {
        int r = r0 + ty * 4 + i;
        int p = r >> 5;
        int b = r & 31;
#pragma unroll
        for (int jj = 0; jj < 2; jj++) {
            int j = j0 + tx * 2 + jj;
            long girow;
            if (LAYER == 0)
                girow = ((long)(m * Ss + t) * Bb + b) * Gg;
            else
                girow = ((long)((m * Pp + p) * Ss + t) * Bb + b) * Gg;
            float gir = gi[girow + j];
            float giz = gi[girow + Hh + j];
            float gin = gi[girow + 2 * Hh + j];
            float ghr = acc[i][0][jj] + bhh[m * Gg + j];
            float ghz = acc[i][1][jj] + bhh[m * Gg + Hh + j];
            float ghn = acc[i][2][jj] + bhh[m * Gg + 2 * Hh + j];
            float rg = sigmoidf_(gir + ghr);
            float zg = sigmoidf_(giz + ghz);
            float ng = tanhf(gin + rg * ghn);
            float hold = Ab[(long)r * Hh + j];
            float hnew = (1.0f - zg) * ng + zg * hold;
            hnext[(long)m * Rr * Hh + (long)r * Hh + j] = hnew;
            long oidx = (((long)(m * Pp + p) * Ss + t) * Bb + b) * Hh + j;
            if (LAYER == 0)
                outact[oidx] = hnew * dm[oidx];
            else
                outact[oidx] = fmaxf(hnew, 0.f) + 0.01f * fminf(hnew, 0.f);
        }
    }
}

// ---------------- mean / var over the 16 (m,p) samples ----------------
__global__ void meanvar_kernel(const float* __restrict__ preds,
                               float* __restrict__ out_mean, float* __restrict__ out_var)
{
    const int n = Ss * Bb * Oo;
    int idx = blockIdx.x * blockDim.x + threadIdx.x;
    if (idx >= n) return;
    float v[16];
    float s = 0.f;
#pragma unroll
    for (int mp = 0; mp < 16; mp++) {
        v[mp] = preds[(long)mp * n + idx];
        s += v[mp];
    }
    float mu = s * (1.0f / 16.0f);
    float q = 0.f;
#pragma unroll
    for (int mp = 0; mp < 16; mp++) {
        float d = v[mp] - mu;
        q += d * d;
    }
    out_mean[idx] = mu;
    out_var[idx]  = q * (1.0f / 15.0f);
}

// ---------------- host launch ----------------
extern "C" void kernel_launch(void* const* d_in, const int* in_sizes, int n_in,
                              void* d_out, int out_size)
{
    const float* input  = (const float*)d_in[0];
    const float* hidden = (const float*)d_in[1];
    const float* w_ih0  = (const float*)d_in[2];
    const float* w_hh0  = (const float*)d_in[3];
    const float* b_ih0  = (const float*)d_in[4];
    const float* b_hh0  = (const float*)d_in[5];
    const float* w_ih1  = (const float*)d_in[6];
    const float* w_hh1  = (const float*)d_in[7];
    const float* b_ih1  = (const float*)d_in[8];
    const float* b_hh1  = (const float*)d_in[9];
    const float* lin_w  = (const float*)d_in[10];
    const float* lin_b  = (const float*)d_in[11];
    const float* dm     = (const float*)d_in[12];

    float* out = (float*)d_out;
    float* out_mean   = out;
    float* out_var    = out + (size_t)Ss * Bb * Oo;
    float* preds      = out + 2 * (size_t)Ss * Bb * Oo;
    float* hidden_out = preds + (size_t)Mm * Pp * Ss * Bb * Oo;

    float *gi0, *y0m, *gi1, *a1, *h0a, *h0b, *h1a, *h1b;
    cudaGetSymbolAddress((void**)&gi0, g_gi0);
    cudaGetSymbolAddress((void**)&y0m, g_y0m);
    cudaGetSymbolAddress((void**)&gi1, g_gi1);
    cudaGetSymbolAddress((void**)&a1,  g_a1);
    cudaGetSymbolAddress((void**)&h0a, g_h0a);
    cudaGetSymbolAddress((void**)&h0b, g_h0b);
    cudaGetSymbolAddress((void**)&h1a, g_h1a);
    cudaGetSymbolAddress((void**)&h1b, g_h1b);

    // 1) init hidden
    init_hidden_kernel<<<(Mm*Pp*Bb*Hh + 255) / 256, 256>>>(hidden, h0a, h1a);

    // 2) gi0 = input @ w_ih0^T + b_ih0  (TF32 tensor cores)
    {
        dim3 grid(Gg / 64, (Ss * Bb) / 128, Mm);
        gemm_tf32_bias<<<grid, 256>>>(input, 0L,
                                      w_ih0, (long)Gg * Ii,
                                      b_ih0, Gg,
                                      gi0, (long)Ss * Bb * Gg,
                                      Ss * Bb, Gg, Ii);
    }

    // 3) layer-0 recurrence
    {
        dim3 grid(Hh / 32, Rr / 64, Mm);
        float* hp = h0a; float* hn = h0b;
        for (int t = 0; t < Ss; t++) {
            gru_step_kernel<0><<<grid, 256>>>(hp, hn, gi0, w_hh0, b_hh0, dm, y0m, t);
            float* tmp = hp; hp = hn; hn = tmp;
        }
    }

    // 4) gi1 = y0m @ w_ih1^T + b_ih1 (TF32)
    {
        dim3 grid(Gg / 64, (Pp * Ss * Bb) / 128, Mm);
        gemm_tf32_bias<<<grid, 256>>>(y0m, (long)Pp * Ss * Bb * Hh,
                                      w_ih1, (long)Gg * Hh,
                                      b_ih1, Gg,
                                      gi1, (long)Pp * Ss * Bb * Gg,
                                      Pp * Ss * Bb, Gg, Hh);
    }

    // 5) layer-1 recurrence
    {
        dim3 grid(Hh / 32, Rr / 64, Mm);
        float* hp = h1a; float* hn = h1b;
        for (int t = 0; t < Ss; t++) {
            gru_step_kernel<1><<<grid, 256>>>(hp, hn, gi1, w_hh1, b_hh1, nullptr, a1, t);
            float* tmp = hp; hp = hn; hn = tmp;
        }
    }

    // 6) preds = a1 @ lin_w^T + lin_b (TF32)
    {
        dim3 grid(Oo / 64, (Pp * Ss * Bb) / 128, Mm);
        gemm_tf32_bias<<<grid, 256>>>(a1, (long)Pp * Ss * Bb * Hh,
                                      lin_w, (long)Oo * Hh,
                                      lin_b, Oo,
                                      preds, (long)Pp * Ss * Bb * Oo,
                                      Pp * Ss * Bb, Oo, Hh);
    }

    // 7) mean / var
    meanvar_kernel<<<(Ss * Bb * Oo + 255) / 256, 256>>>(preds, out_mean, out_var);

    // 8) hidden out
    hidden_out_kernel<<<(Mm*Pp*Bb*Hh + 255) / 256, 256>>>(h0a, h1a, hidden_out);
}

// round 3
// speedup vs baseline: 2.0395x; 1.4893x over previous
#include <cuda_runtime.h>
#include <math.h>
#include <stdint.h>

// Problem constants
#define Mm 4
#define Pp 4
#define Ll 2
#define Ss 256
#define Bb 32
#define Ii 256
#define Hh 512
#define Oo 256
#define Gg (3*Hh)     // 1536
#define Rr (Pp*Bb)    // 128 rows per model in the recurrence

// ---------------- scratch (device globals; no allocation) ----------------
__device__ float g_gi0[(size_t)Mm*Ss*Bb*Gg];
__device__ float g_y0m[(size_t)Mm*Pp*Ss*Bb*Hh];
__device__ float g_gi1[(size_t)Mm*Pp*Ss*Bb*Gg];
__device__ float g_a1 [(size_t)Mm*Pp*Ss*Bb*Hh];
__device__ float g_h0a[Mm*Rr*Hh];
__device__ float g_h0b[Mm*Rr*Hh];
__device__ float g_h1a[Mm*Rr*Hh];
__device__ float g_h1b[Mm*Rr*Hh];
// hi/lo split of recurrent weights, both layers: [layer][M][3H][H]
__device__ float g_whh_hi[2 * Mm * Gg * Hh];
__device__ float g_whh_lo[2 * Mm * Gg * Hh];

// ---------------- helpers ----------------
__device__ __forceinline__ float tf32r(float x) {
    uint32_t u;
    asm("cvt.rna.tf32.f32 %0, %1;" : "=r"(u) : "f"(x));
    return __uint_as_float(u);
}

__device__ __forceinline__ void mma_tf32(float c[4], const uint32_t a[4], const uint32_t b[2]) {
    asm volatile(
        "mma.sync.aligned.m16n8k8.row.col.f32.tf32.tf32.f32 "
        "{%0,%1,%2,%3},{%4,%5,%6,%7},{%8,%9},{%0,%1,%2,%3};"
        : "+f"(c[0]), "+f"(c[1]), "+f"(c[2]), "+f"(c[3])
        : "r"(a[0]), "r"(a[1]), "r"(a[2]), "r"(a[3]), "r"(b[0]), "r"(b[1]));
}

__device__ __forceinline__ float sigmoidf_(float x) { return 1.0f / (1.0f + expf(-x)); }

// ---------------- init hidden ----------------
__global__ void init_hidden_kernel(const float* __restrict__ hidden,
                                   float* __restrict__ h0, float* __restrict__ h1)
{
    int idx = blockIdx.x * blockDim.x + threadIdx.x;
    const int n = Mm*Pp*Bb*Hh;
    if (idx >= n) return;
    int mp  = idx / (Bb*Hh);
    int rem = idx % (Bb*Hh);
    h0[idx] = hidden[((size_t)mp*Ll + 0)*Bb*Hh + rem];
    h1[idx] = hidden[((size_t)mp*Ll + 1)*Bb*Hh + rem];
}

__global__ void hidden_out_kernel(const float* __restrict__ h0, const float* __restrict__ h1,
                                  float* __restrict__ out)
{
    int idx = blockIdx.x * blockDim.x + threadIdx.x;
    const int n = Mm*Pp*Bb*Hh;
    if (idx >= n) return;
    int mp  = idx / (Bb*Hh);
    int rem = idx % (Bb*Hh);
    out[((size_t)mp*Ll + 0)*Bb*Hh + rem] = h0[idx];
    out[((size_t)mp*Ll + 1)*Bb*Hh + rem] = h1[idx];
}

// ---------------- split weights into tf32 hi/lo ----------------
__global__ void split_hilo_kernel(const float* __restrict__ w0, const float* __restrict__ w1,
                                  float* __restrict__ hi, float* __restrict__ lo)
{
    const int n = Mm * Gg * Hh;
    int idx = blockIdx.x * blockDim.x + threadIdx.x;
    if (idx >= 2 * n) return;
    float x = (idx < n) ? w0[idx] : w1[idx - n];
    float h = tf32r(x);
    hi[idx] = h;
    lo[idx] = tf32r(x - h);
}

// ================= TF32 tensor-core GEMM with bias (feedforward) =================
__global__ __launch_bounds__(256) void gemm_tf32_bias(
    const float* __restrict__ A, long aStride,
    const float* __restrict__ W, long wStride,
    const float* __restrict__ bias, int bStride,
    float* __restrict__ C, long cStride,
    int rows, int N, int K)
{
    const int batch = blockIdx.z;
    A    += (long)batch * aStride;
    W    += (long)batch * wStride;
    bias += (long)batch * bStride;
    C    += (long)batch * cStride;

    const int r0 = blockIdx.y * 128;
    const int n0 = blockIdx.x * 64;

    __shared__ float As[128][36];
    __shared__ float Bs[64][36];

    const int tid  = threadIdx.x;
    const int lane = tid & 31;
    const int w    = tid >> 5;
    const int wr   = w >> 1;
    const int wc   = w & 1;
    const int gID  = lane >> 2;
    const int tig  = lane & 3;

    float c[2][4][4];
#pragma unroll
    for (int mi = 0; mi < 2; mi++)
#pragma unroll
        for (int ni = 0; ni < 4; ni++)
#pragma unroll
            for (int q = 0; q < 4; q++) c[mi][ni][q] = 0.f;

    for (int k0 = 0; k0 < K; k0 += 32) {
#pragma unroll
        for (int l = 0; l < 4; l++) {
            int f = tid + l * 256;
            int row = f >> 3;
            int kg  = f & 7;
            float4 v = *reinterpret_cast<const float4*>(&A[(long)(r0 + row) * K + k0 + kg * 4]);
            float4 t;
            t.x = tf32r(v.x); t.y = tf32r(v.y); t.z = tf32r(v.z); t.w = tf32r(v.w);
            *reinterpret_cast<float4*>(&As[row][kg * 4]) = t;
        }
#pragma unroll
        for (int l = 0; l < 2; l++) {
            int f = tid + l * 256;
            int col = f >> 3;
            int kg  = f & 7;
            float4 v = *reinterpret_cast<const float4*>(&W[(long)(n0 + col) * K + k0 + kg * 4]);
            float4 t;
            t.x = tf32r(v.x); t.y = tf32r(v.y); t.z = tf32r(v.z); t.w = tf32r(v.w);
            *reinterpret_cast<float4*>(&Bs[col][kg * 4]) = t;
        }
        __syncthreads();

#pragma unroll
        for (int k8 = 0; k8 < 4; k8++) {
            const int kb = k8 * 8;
            uint32_t af[2][4];
#pragma unroll
            for (int mi = 0; mi < 2; mi++) {
                int rb = wr * 32 + mi * 16 + gID;
                af[mi][0] = __float_as_uint(As[rb    ][kb + tig]);
                af[mi][1] = __float_as_uint(As[rb + 8][kb + tig]);
                af[mi][2] = __float_as_uint(As[rb    ][kb + 4 + tig]);
                af[mi][3] = __float_as_uint(As[rb + 8][kb + 4 + tig]);
            }
            uint32_t bf[4][2];
#pragma unroll
            for (int ni = 0; ni < 4; ni++) {
                int cb = wc * 32 + ni * 8 + gID;
                bf[ni][0] = __float_as_uint(Bs[cb][kb + tig]);
                bf[ni][1] = __float_as_uint(Bs[cb][kb + 4 + tig]);
            }
#pragma unroll
            for (int mi = 0; mi < 2; mi++)
#pragma unroll
                for (int ni = 0; ni < 4; ni++)
                    mma_tf32(c[mi][ni], af[mi], bf[ni]);
        }
        __syncthreads();
    }

#pragma unroll
    for (int mi = 0; mi < 2; mi++) {
#pragma unroll
        for (int ni = 0; ni < 4; ni++) {
            int row = r0 + wr * 32 + mi * 16 + gID;
            int col = n0 + wc * 32 + ni * 8 + 2 * tig;
            float b0 = bias[col], b1 = bias[col + 1];
            float2 v0 = make_float2(c[mi][ni][0] + b0, c[mi][ni][1] + b1);
            float2 v1 = make_float2(c[mi][ni][2] + b0, c[mi][ni][3] + b1);
            *reinterpret_cast<float2*>(&C[(long)row * N + col]) = v0;
            *reinterpret_cast<float2*>(&C[(long)(row + 8) * N + col]) = v1;
        }
    }
}

// ================= fused GRU step: 3xTF32 tensor-core gh GEMM + gates =================
// grid = 128 blocks: m = bx>>5, j-slice of 16 (j0 = (bx&31)*16). 256 threads = 8 warps.
// Each warp: m16 row-stripe (rows w*16..w*16+15), 48 gate-cols (3 gates x 16 j) = 6 n8 tiles.
template<int LAYER>
__global__ __launch_bounds__(256) void gru_step_mma(
    const float* __restrict__ hprev,
    float* __restrict__ hnext,
    const float* __restrict__ gi,
    const float* __restrict__ whh_hi,   // layer base already applied
    const float* __restrict__ whh_lo,
    const float* __restrict__ bhh,
    const float* __restrict__ dm,
    float* __restrict__ outact,
    int t)
{
    const int bx = blockIdx.x;
    const int m  = bx >> 5;
    const int j0 = (bx & 31) * 16;

    __shared__ float As[128][36];   // fp32 h chunk [row][k]
    __shared__ float Wh[48][36];    // hi  [gatecol][k]
    __shared__ float Wl[48][36];    // lo

    const int tid  = threadIdx.x;
    const int lane = tid & 31;
    const int w    = tid >> 5;
    const int gID  = lane >> 2;
    const int tig  = lane & 3;

    const float* Ab  = hprev  + (long)m * Rr * Hh;
    const float* Whb = whh_hi + (long)m * Gg * Hh;
    const float* Wlb = whh_lo + (long)m * Gg * Hh;

    float c[6][4];
#pragma unroll
    for (int tI = 0; tI < 6; tI++)
#pragma unroll
        for (int q = 0; q < 4; q++) c[tI][q] = 0.f;

    // per-thread load slots
    // A: 128 rows x 32k = 1024 float4, 4/thread
    int arow[4], akg[4];
#pragma unroll
    for (int l = 0; l < 4; l++) {
        int f = tid + l * 256;
        arow[l] = f >> 3;
        akg[l]  = f & 7;
    }
    // W: 2 arrays x 48 cols x 8 f4 = 768 float4, 3/thread
    int wsel[3], wcol[3], wkg[3];
    const float* pW[3];
#pragma unroll
    for (int l = 0; l < 3; l++) {
        int f = tid + l * 256;
        wsel[l] = f / 384;          // 0 = hi, 1 = lo
        int idx = f % 384;
        wcol[l] = idx >> 3;         // 0..47
        wkg[l]  = idx & 7;
        int gate = wcol[l] >> 4;
        int jloc = wcol[l] & 15;
        const float* base = wsel[l] ? Wlb : Whb;
        pW[l] = base + (long)(gate * Hh + j0 + jloc) * Hh + wkg[l] * 4;
    }

    float4 aReg[4], wReg[3];
    // prologue: chunk 0
#pragma unroll
    for (int l = 0; l < 4; l++)
        aReg[l] = *reinterpret_cast<const float4*>(&Ab[(long)arow[l] * Hh + akg[l] * 4]);
#pragma unroll
    for (int l = 0; l < 3; l++)
        wReg[l] = *reinterpret_cast<const float4*>(pW[l]);

#pragma unroll
    for (int l = 0; l < 4; l++)
        *reinterpret_cast<float4*>(&As[arow[l]][akg[l] * 4]) = aReg[l];
#pragma unroll
    for (int l = 0; l < 3; l++) {
        float* dst = wsel[l] ? &Wl[wcol[l]][wkg[l] * 4] : &Wh[wcol[l]][wkg[l] * 4];
        *reinterpret_cast<float4*>(dst) = wReg[l];
    }
    __syncthreads();

    const int rb = w * 16 + gID;

    for (int kt = 0; kt < 16; kt++) {
        // prefetch next chunk
        if (kt < 15) {
            const int off = (kt + 1) * 32;
#pragma unroll
            for (int l = 0; l < 4; l++)
                aReg[l] = *reinterpret_cast<const float4*>(&Ab[(long)arow[l] * Hh + off + akg[l] * 4]);
#pragma unroll
            for (int l = 0; l < 3; l++)
                wReg[l] = *reinterpret_cast<const float4*>(pW[l] + off);
        }

#pragma unroll
        for (int k8 = 0; k8 < 4; k8++) {
            const int kb = k8 * 8;
            float x0 = As[rb    ][kb + tig];
            float x1 = As[rb + 8][kb + tig];
            float x2 = As[rb    ][kb + 4 + tig];
            float x3 = As[rb + 8][kb + 4 + tig];
            float h0 = tf32r(x0), h1 = tf32r(x1), h2 = tf32r(x2), h3 = tf32r(x3);
            uint32_t ahi[4] = {__float_as_uint(h0), __float_as_uint(h1),
                               __float_as_uint(h2), __float_as_uint(h3)};
            uint32_t alo[4] = {__float_as_uint(tf32r(x0 - h0)), __float_as_uint(tf32r(x1 - h1)),
                               __float_as_uint(tf32r(x2 - h2)), __float_as_uint(tf32r(x3 - h3))};
#pragma unroll
            for (int tI = 0; tI < 6; tI++) {
                int cc = tI * 8 + gID;
                uint32_t bh[2] = {__float_as_uint(Wh[cc][kb + tig]),
                                  __float_as_uint(Wh[cc][kb + 4 + tig])};
                uint32_t bl[2] = {__float_as_uint(Wl[cc][kb + tig]),
                                  __float_as_uint(Wl[cc][kb + 4 + tig])};
                mma_tf32(c[tI], ahi, bh);
                mma_tf32(c[tI], ahi, bl);
                mma_tf32(c[tI], alo, bh);
            }
        }

        if (kt < 15) {
            __syncthreads();   // all mma done reading current smem
#pragma unroll
            for (int l = 0; l < 4; l++)
                *reinterpret_cast<float4*>(&As[arow[l]][akg[l] * 4]) = aReg[l];
#pragma unroll
            for (int l = 0; l < 3; l++) {
                float* dst = wsel[l] ? &Wl[wcol[l]][wkg[l] * 4] : &Wh[wcol[l]][wkg[l] * 4];
                *reinterpret_cast<float4*>(dst) = wReg[l];
            }
            __syncthreads();
        }
    }

    // ---------- epilogue: gates + h update ----------
    // thread holds, for rows r = w*16+gID (+8) and u in {0,1}:
    //   r-gate: c[0+u][..], z-gate: c[2+u][..], n-gate: c[4+u][..]
    //   cols j = j0 + u*8 + 2*tig + jj
#pragma unroll
    for (int rh = 0; rh < 2; rh++) {
        int r = w * 16 + gID + rh * 8;
        int p = r >> 5;
        int b = r & 31;
        long girow;
        if (LAYER == 0)
            girow = ((long)(m * Ss + t) * Bb + b) * Gg;
        else
            girow = ((long)((m * Pp + p) * Ss + t) * Bb + b) * Gg;
        long obase = (((long)(m * Pp + p) * Ss + t) * Bb + b) * Hh;
#pragma unroll
        for (int u = 0; u < 2; u++) {
#pragma unroll
            for (int jj = 0; jj < 2; jj++) {
                int j = j0 + u * 8 + 2 * tig + jj;
                int q = rh * 2 + jj;
                float gir = gi[girow + j];
                float giz = gi[girow + Hh + j];
                float gin = gi[girow + 2 * Hh + j];
                float ghr = c[0 + u][q] + bhh[m * Gg + j];
                float ghz = c[2 + u][q] + bhh[m * Gg + Hh + j];
                float ghn = c[4 + u][q] + bhh[m * Gg + 2 * Hh + j];
                float rg = sigmoidf_(gir + ghr);
                float zg = sigmoidf_(giz + ghz);
                float ng = tanhf(gin + rg * ghn);
                float hold = Ab[(long)r * Hh + j];
                float hnew = (1.0f - zg) * ng + zg * hold;
                hnext[(long)m * Rr * Hh + (long)r * Hh + j] = hnew;
                long oidx = obase + j;
                if (LAYER == 0)
                    outact[oidx] = hnew * dm[oidx];
                else
                    outact[oidx] = fmaxf(hnew, 0.f) + 0.01f * fminf(hnew, 0.f);
            }
        }
    }
}

// ---------------- mean / var ----------------
__global__ void meanvar_kernel(const float* __restrict__ preds,
                               float* __restrict__ out_mean, float* __restrict__ out_var)
{
    const int n = Ss * Bb * Oo;
    int idx = blockIdx.x * blockDim.x + threadIdx.x;
    if (idx >= n) return;
    float v[16];
    float s = 0.f;
#pragma unroll
    for (int mp = 0; mp < 16; mp++) {
        v[mp] = preds[(long)mp * n + idx];
        s += v[mp];
    }
    float mu = s * (1.0f / 16.0f);
    float q = 0.f;
#pragma unroll
    for (int mp = 0; mp < 16; mp++) {
        float d = v[mp] - mu;
        q += d * d;
    }
    out_mean[idx] = mu;
    out_var[idx]  = q * (1.0f / 15.0f);
}

// ---------------- host launch ----------------
extern "C" void kernel_launch(void* const* d_in, const int* in_sizes, int n_in,
                              void* d_out, int out_size)
{
    const float* input  = (const float*)d_in[0];
    const float* hidden = (const float*)d_in[1];
    const float* w_ih0  = (const float*)d_in[2];
    const float* w_hh0  = (const float*)d_in[3];
    const float* b_ih0  = (const float*)d_in[4];
    const float* b_hh0  = (const float*)d_in[5];
    const float* w_ih1  = (const float*)d_in[6];
    const float* w_hh1  = (const float*)d_in[7];
    const float* b_ih1  = (const float*)d_in[8];
    const float* b_hh1  = (const float*)d_in[9];
    const float* lin_w  = (const float*)d_in[10];
    const float* lin_b  = (const float*)d_in[11];
    const float* dm     = (const float*)d_in[12];

    float* out = (float*)d_out;
    float* out_mean   = out;
    float* out_var    = out + (size_t)Ss * Bb * Oo;
    float* preds      = out + 2 * (size_t)Ss * Bb * Oo;
    float* hidden_out = preds + (size_t)Mm * Pp * Ss * Bb * Oo;

    float *gi0, *y0m, *gi1, *a1, *h0a, *h0b, *h1a, *h1b, *whh_hi, *whh_lo;
    cudaGetSymbolAddress((void**)&gi0, g_gi0);
    cudaGetSymbolAddress((void**)&y0m, g_y0m);
    cudaGetSymbolAddress((void**)&gi1, g_gi1);
    cudaGetSymbolAddress((void**)&a1,  g_a1);
    cudaGetSymbolAddress((void**)&h0a, g_h0a);
    cudaGetSymbolAddress((void**)&h0b, g_h0b);
    cudaGetSymbolAddress((void**)&h1a, g_h1a);
    cudaGetSymbolAddress((void**)&h1b, g_h1b);
    cudaGetSymbolAddress((void**)&whh_hi, g_whh_hi);
    cudaGetSymbolAddress((void**)&whh_lo, g_whh_lo);

    const int WN = Mm * Gg * Hh;

    // 0) split recurrent weights into hi/lo
    split_hilo_kernel<<<(2 * WN + 255) / 256, 256>>>(w_hh0, w_hh1, whh_hi, whh_lo);

    // 1) init hidden
    init_hidden_kernel<<<(Mm*Pp*Bb*Hh + 255) / 256, 256>>>(hidden, h0a, h1a);

    // 2) gi0 = input @ w_ih0^T + b_ih0  (TF32)
    {
        dim3 grid(Gg / 64, (Ss * Bb) / 128, Mm);
        gemm_tf32_bias<<<grid, 256>>>(input, 0L,
                                      w_ih0, (long)Gg * Ii,
                                      b_ih0, Gg,
                                      gi0, (long)Ss * Bb * Gg,
                                      Ss * Bb, Gg, Ii);
    }

    // 3) layer-0 recurrence (3xTF32 tensor cores)
    {
        float* hp = h0a; float* hn = h0b;
        for (int t = 0; t < Ss; t++) {
            gru_step_mma<0><<<128, 256>>>(hp, hn, gi0, whh_hi, whh_lo, b_hh0, dm, y0m, t);
            float* tmp = hp; hp = hn; hn = tmp;
        }
    }

    // 4) gi1 = y0m @ w_ih1^T + b_ih1 (TF32)
    {
        dim3 grid(Gg / 64, (Pp * Ss * Bb) / 128, Mm);
        gemm_tf32_bias<<<grid, 256>>>(y0m, (long)Pp * Ss * Bb * Hh,
                                      w_ih1, (long)Gg * Hh,
                                      b_ih1, Gg,
                                      gi1, (long)Pp * Ss * Bb * Gg,
                                      Pp * Ss * Bb, Gg, Hh);
    }

    // 5) layer-1 recurrence
    {
        float* hp = h1a; float* hn = h1b;
        for (int t = 0; t < Ss; t++) {
            gru_step_mma<1><<<128, 256>>>(hp, hn, gi1, whh_hi + WN, whh_lo + WN,
                                          b_hh1, nullptr, a1, t);
            float* tmp = hp; hp = hn; hn = tmp;
        }
    }

    // 6) preds = a1 @ lin_w^T + lin_b (TF32)
    {
        dim3 grid(Oo / 64, (Pp * Ss * Bb) / 128, Mm);
        gemm_tf32_bias<<<grid, 256>>>(a1, (long)Pp * Ss * Bb * Hh,
                                      lin_w, (long)Oo * Hh,
                                      lin_b, Oo,
                                      preds, (long)Pp * Ss * Bb * Oo,
                                      Pp * Ss * Bb, Oo, Hh);
    }

    // 7) mean / var
    meanvar_kernel<<<(Ss * Bb * Oo + 255) / 256, 256>>>(preds, out_mean, out_var);

    // 8) hidden out
    hidden_out_kernel<<<(Mm*Pp*Bb*Hh + 255) / 256, 256>>>(h0a, h1a, hidden_out);
}